// round 16
// baseline (speedup 1.0000x reference)
#include <cuda_runtime.h>
#include <cuda_fp16.h>
#include <math.h>
#include <stdint.h>

// ---------------- problem constants ----------------
constexpr int Bv  = 16;
constexpr int Cv  = 512;
constexpr int Lv  = 2048;
constexpr int Hv  = 8;
constexpr int Dhv = 64;

// ---------------- fp16 mma GEMM config ----------------
constexpr int BM  = 128;
constexpr int BN  = 128;
constexpr int BKK = 32;
constexpr int A_HALFS  = BM * 40;            // 80B rows, conflict-free
constexpr int B_HALFS  = BKK * 136;          // 272B rows, conflict-free
constexpr int STAGE_BYTES = (A_HALFS + B_HALFS) * 2;   // 18944
constexpr int STAGES = 4;
constexpr int SMEM_GEMM = STAGES * STAGE_BYTES;        // 75776

// ---------------- attention smem config ----------------
constexpr int TL = 32;                       // l-positions per block
constexpr int KV_PITCH = 1032;               // halfs; 2064B = 516 words ≡ 4 (mod 32)
constexpr int ATTN_SMEM = (TL + 2) * KV_PITCH * 2;   // 70176 bytes

// ---------------- scratch ----------------
__device__ __half g_QT[16777216];
__device__ __half g_XT[16777216];
__device__ __half g_Q[16777216];
__device__ __half g_KV[33554432];  // [M,1024]: cols 0-511 K, 512-1023 V
__device__ __half g_O[16777216];
__device__ __half g_Y[16777216];
__device__ __half g_U[33554432];
__device__ __half g_WT[2097152];
__device__ float  g_BKV[1024];
__device__ float  g_S1[Bv*Cv], g_T1[Bv*Cv];
__device__ __half g_S2h[Bv*Cv], g_T2h[Bv*Cv];   // norm2 affine, fp16 tables

constexpr int WQ_OFF  = 0;
constexpr int WKV_OFF = 262144;    // interleaved [512 x 1024]
constexpr int WO_OFF  = 786432;
constexpr int WFC_OFF = 1048576;
constexpr int WPR_OFF = 1572864;

// ---------------- helpers ----------------
__device__ __forceinline__ uint32_t smem_u32(const void* p) {
    uint32_t a;
    asm("{ .reg .u64 t; cvta.to.shared.u64 t, %1; cvt.u32.u64 %0, t; }" : "=r"(a) : "l"(p));
    return a;
}
__device__ __forceinline__ uint32_t h2u(__half2 h) {
    union { __half2 h; uint32_t u; } c; c.h = h; return c.u;
}
__device__ __forceinline__ __half2 u2h(uint32_t u) {
    union { uint32_t u; __half2 h; } c; c.u = u; return c.h;
}
__device__ __forceinline__ void cpa16(uint32_t dst, const void* src) {
    asm volatile("cp.async.cg.shared.global [%0], [%1], 16;" :: "r"(dst), "l"(src) : "memory");
}
template<int NW>
__device__ __forceinline__ void cpwait() {
    asm volatile("cp.async.wait_group %0;" :: "n"(NW) : "memory");
}

#define LDSM4(r0, r1, r2, r3, addr)                                          \
    asm volatile("ldmatrix.sync.aligned.m8n8.x4.shared.b16 {%0,%1,%2,%3}, [%4];" \
        : "=r"(r0), "=r"(r1), "=r"(r2), "=r"(r3) : "r"(addr))

#define LDSM4T(r0, r1, r2, r3, addr)                                         \
    asm volatile("ldmatrix.sync.aligned.m8n8.x4.trans.shared.b16 {%0,%1,%2,%3}, [%4];" \
        : "=r"(r0), "=r"(r1), "=r"(r2), "=r"(r3) : "r"(addr))

#define MMA16(d, a, b0, b1)                                                  \
    asm volatile("mma.sync.aligned.m16n8k16.row.col.f32.f16.f16.f32 "        \
        "{%0,%1,%2,%3}, {%4,%5,%6,%7}, {%8,%9}, {%0,%1,%2,%3};"              \
        : "+f"((d)[0]), "+f"((d)[1]), "+f"((d)[2]), "+f"((d)[3])             \
        : "r"((a)[0]), "r"((a)[1]), "r"((a)[2]), "r"((a)[3]),                \
          "r"(b0), "r"(b1))

// ---------------- instance-norm stats over rows of x (B,C,L) -------------
__global__ void rowstats_kernel(const float* __restrict__ x,
                                const float* __restrict__ gamma,
                                const float* __restrict__ beta,
                                float* __restrict__ s, float* __restrict__ t)
{
    int row = blockIdx.x;
    const float4* p = (const float4*)(x + (size_t)row * Lv);
    float sum = 0.f, sq = 0.f;
    for (int i = threadIdx.x; i < Lv / 4; i += blockDim.x) {
        float4 v = p[i];
        sum += v.x + v.y + v.z + v.w;
        sq  += v.x*v.x + v.y*v.y + v.z*v.z + v.w*v.w;
    }
    __shared__ float ssum[8], ssq[8];
    for (int o = 16; o; o >>= 1) {
        sum += __shfl_down_sync(0xffffffffu, sum, o);
        sq  += __shfl_down_sync(0xffffffffu, sq,  o);
    }
    int wid = threadIdx.x >> 5, lane = threadIdx.x & 31;
    if (lane == 0) { ssum[wid] = sum; ssq[wid] = sq; }
    __syncthreads();
    if (wid == 0) {
        sum = lane < (blockDim.x >> 5) ? ssum[lane] : 0.f;
        sq  = lane < (blockDim.x >> 5) ? ssq[lane]  : 0.f;
        for (int o = 4; o; o >>= 1) {
            sum += __shfl_down_sync(0xffffffffu, sum, o);
            sq  += __shfl_down_sync(0xffffffffu, sq,  o);
        }
        if (lane == 0) {
            float mean = sum / (float)Lv;
            float var  = sq / (float)Lv - mean * mean;
            float rstd = rsqrtf(var + 1e-5f);
            int c = row % Cv;
            float sv = gamma[c] * rstd;
            s[row] = sv;
            t[row] = beta[c] - mean * sv;
        }
    }
}

// ---------------- instance-norm stats over columns of y (B*L, C) half ----
// v2: lane loads __half2 (warp covers 64 contiguous channels = 128B line)
// grid (Cv/64, Bv), block 256 = 32 lanes x 8 l-slices
__global__ void colstats_kernel(const __half* __restrict__ y,
                                const float* __restrict__ gamma,
                                const float* __restrict__ beta,
                                __half* __restrict__ sh, __half* __restrict__ th)
{
    int b    = blockIdx.y;
    int c0   = blockIdx.x * 64;
    int lane = threadIdx.x & 31;
    int wj   = threadIdx.x >> 5;            // 0..7
    const __half2* base = (const __half2*)(y + (size_t)b * Lv * Cv + c0 + lane * 2);
    float sx = 0.f, sy = 0.f, qx = 0.f, qy = 0.f;
    #pragma unroll 4
    for (int l = wj; l < Lv; l += 8) {
        float2 v = __half22float2(base[(size_t)l * (Cv / 2)]);
        sx += v.x; sy += v.y;
        qx += v.x * v.x; qy += v.y * v.y;
    }
    __shared__ float S[8][64], Q[8][64];
    S[wj][lane * 2]     = sx; S[wj][lane * 2 + 1] = sy;
    Q[wj][lane * 2]     = qx; Q[wj][lane * 2 + 1] = qy;
    __syncthreads();
    if (wj < 2) {
        int cc = wj * 32 + lane;            // 0..63
        float sum = 0.f, sq = 0.f;
        #pragma unroll
        for (int j = 0; j < 8; j++) { sum += S[j][cc]; sq += Q[j][cc]; }
        float mean = sum / (float)Lv;
        float var  = sq / (float)Lv - mean * mean;
        float rstd = rsqrtf(var + 1e-5f);
        int c = c0 + cc;
        float sv = gamma[c] * rstd;
        sh[b * Cv + c] = __float2half(sv);
        th[b * Cv + c] = __float2half(beta[c] - mean * sv);
    }
}

// ---------------- merged transpose (B,C,L) f32 -> (B*L,C) f16 ------------
__global__ void transpose_qx(const float* __restrict__ qsrc,
                             const float* __restrict__ xsrc,
                             const float* __restrict__ s,
                             const float* __restrict__ t,
                             __half* __restrict__ QT,
                             __half* __restrict__ XT)
{
    __shared__ float sm[32][33];
    int b  = blockIdx.z;
    int c0 = blockIdx.y * 32;
    int l0 = blockIdx.x * 32;
    int tx = threadIdx.x, ty = threadIdx.y;
    #pragma unroll
    for (int i = 0; i < 4; i++) {
        int c = c0 + ty + i * 8;
        sm[ty + i * 8][tx] = qsrc[((size_t)(b * Cv + c)) * Lv + l0 + tx];
    }
    __syncthreads();
    #pragma unroll
    for (int i = 0; i < 4; i++) {
        int l = l0 + ty + i * 8;
        QT[((size_t)(b * Lv + l)) * Cv + c0 + tx] = __float2half(sm[tx][ty + i * 8]);
    }
    __syncthreads();
    #pragma unroll
    for (int i = 0; i < 4; i++) {
        int c = c0 + ty + i * 8;
        float v = xsrc[((size_t)(b * Cv + c)) * Lv + l0 + tx];
        sm[ty + i * 8][tx] = v * s[b * Cv + c] + t[b * Cv + c];
    }
    __syncthreads();
    #pragma unroll
    for (int i = 0; i < 4; i++) {
        int l = l0 + ty + i * 8;
        XT[((size_t)(b * Lv + l)) * Cv + c0 + tx] = __float2half(sm[tx][ty + i * 8]);
    }
}

// ---------------- all weights fp32 -> fp16 in one pass --------------------
__global__ void w2h_all(const float* __restrict__ Wq, const float* __restrict__ Wk,
                        const float* __restrict__ Wv, const float* __restrict__ Wo,
                        const float* __restrict__ Wfc, const float* __restrict__ Wpr,
                        const float* __restrict__ bk, const float* __restrict__ bv,
                        __half* __restrict__ WT, float* __restrict__ bkv)
{
    int i = blockIdx.x * blockDim.x + threadIdx.x;   // float4 index, 524288 total
    if (i < 1024) bkv[i] = (i < 512) ? bk[i] : bv[i - 512];
    const float* src; size_t dsth;
    if (i < 65536)       { src = Wq + (size_t)i * 4;  dsth = WQ_OFF + (size_t)i * 4; }
    else if (i < 131072) { int rel = i - 65536;  int k = rel >> 7, n4 = rel & 127;
                           src = Wk + (size_t)rel * 4;
                           dsth = WKV_OFF + (size_t)k * 1024 + n4 * 4; }
    else if (i < 196608) { int rel = i - 131072; int k = rel >> 7, n4 = rel & 127;
                           src = Wv + (size_t)rel * 4;
                           dsth = WKV_OFF + (size_t)k * 1024 + 512 + n4 * 4; }
    else if (i < 262144) { int rel = i - 196608; src = Wo + (size_t)rel * 4;
                           dsth = WO_OFF + (size_t)rel * 4; }
    else if (i < 393216) { int rel = i - 262144; src = Wfc + (size_t)rel * 4;
                           dsth = WFC_OFF + (size_t)rel * 4; }
    else                 { int rel = i - 393216; src = Wpr + (size_t)rel * 4;
                           dsth = WPR_OFF + (size_t)rel * 4; }
    float4 v = *(const float4*)src;
    *(__half2*)(WT + dsth)     = __floats2half2_rn(v.x, v.y);
    *(__half2*)(WT + dsth + 2) = __floats2half2_rn(v.z, v.w);
}

// ---------------- fp16 mma.sync GEMM with coalesced smem epilogue ---------
// Y = act( A'[M,K]h @ W[K,N]h + bias_f ),  A' = ANORM ? A*s+t (per b,k) : A
// ACT 0: none (half out)  ACT 1: QuickGELU (half out)
// ACT 2: residual + transpose to (B,C,L) f32 out
// ACT 3: combined Q|KV launch — blockIdx.x<4 uses (A,W,bias,Yv,N=512),
//        otherwise (A2,W2,bias2,Yv2,N=1024); epilogue = ACT0 path.
// 4-stage cp.async pipeline, prefetch depth 3 (R11-validated config).
template<int ACT, bool ANORM>
__global__ void __launch_bounds__(256)
mma_gemm(const __half* __restrict__ A, const __half* __restrict__ W,
         const float* __restrict__ bias, void* __restrict__ Yv,
         int K, int N, const float* __restrict__ xres,
         const __half* __restrict__ nS, const __half* __restrict__ nT,
         const __half* __restrict__ A2, const __half* __restrict__ W2,
         const float* __restrict__ bias2, void* __restrict__ Yv2)
{
    extern __shared__ __align__(16) char smem[];
    const int tid  = threadIdx.x;
    const int bm   = blockIdx.y * BM;
    const int lane = tid & 31, warp = tid >> 5;
    const int wm   = warp & 3, wn = warp >> 2;
    const int r    = lane >> 2, t = lane & 3;
    const uint32_t sbase = smem_u32(smem);
    const int nch = K / BKK;
    const int bb  = bm >> 11;

    // resolve operand set (ACT3 branches per blockIdx.x)
    const __half* Ap = A;  const __half* Wp = W;
    const float*  bp = bias;
    void* Yp = Yv;
    int Np = N;
    int bn = blockIdx.x * BN;
    if (ACT == 3 && blockIdx.x >= 4) {
        Ap = A2; Wp = W2; bp = bias2; Yp = Yv2; Np = 1024;
        bn = (blockIdx.x - 4) * BN;
    }
    if (ANORM) { nS += bb * Cv; nT += bb * Cv; }
    const __half2* nS2 = (const __half2*)nS;
    const __half2* nT2 = (const __half2*)nT;

    float acc[2][8][4];
    #pragma unroll
    for (int mt = 0; mt < 2; mt++)
        #pragma unroll
        for (int nt = 0; nt < 8; nt++)
            #pragma unroll
            for (int j = 0; j < 4; j++) acc[mt][nt][j] = 0.f;

    auto issue = [&](int c) {
        uint32_t as = sbase + (uint32_t)((c % STAGES) * STAGE_BYTES);
        uint32_t bs = as + A_HALFS * 2;
        const __half* ga = Ap + (size_t)bm * K + c * BKK;
        #pragma unroll
        for (int i = 0; i < 2; i++) {
            int id = tid + i * 256;
            int m = id >> 2, q = id & 3;
            cpa16(as + (uint32_t)(m * 80 + q * 16), ga + (size_t)m * K + q * 8);
        }
        const __half* gb = Wp + (size_t)(c * BKK) * Np + bn;
        #pragma unroll
        for (int i = 0; i < 2; i++) {
            int id = tid + i * 256;
            int k = id >> 4, q = id & 15;
            cpa16(bs + (uint32_t)(k * 272 + q * 16), gb + (size_t)k * Np + q * 8);
        }
        asm volatile("cp.async.commit_group;" ::: "memory");
    };

    issue(0); issue(1); issue(2);

    const int l15 = lane & 15;
    const int hi8 = (lane >> 4) << 3;

    for (int c = 0; c < nch; c++) {
        if (c + 2 < nch)      cpwait<2>();
        else if (c + 1 < nch) cpwait<1>();
        else                  cpwait<0>();
        __syncthreads();
        if (c + 3 < nch) issue(c + 3);

        uint32_t as = sbase + (uint32_t)((c % STAGES) * STAGE_BYTES);
        uint32_t bs = as + A_HALFS * 2;

        #pragma unroll
        for (int ks = 0; ks < 2; ks++) {
            uint32_t a[2][4];
            #pragma unroll
            for (int mt = 0; mt < 2; mt++) {
                uint32_t addr = as + (uint32_t)(
                    (wm * 32 + mt * 16 + l15) * 80 + ks * 32 + hi8 * 2);
                LDSM4(a[mt][0], a[mt][1], a[mt][2], a[mt][3], addr);
            }
            if (ANORM) {
                // A-frag k map: regs {0,1} -> k = 2t,2t+1 ; {2,3} -> k+8
                int kidx = c * 16 + ks * 8 + t;      // half2 index
                __half2 sl = nS2[kidx],     tl = nT2[kidx];
                __half2 sh = nS2[kidx + 4], th = nT2[kidx + 4];
                #pragma unroll
                for (int mt = 0; mt < 2; mt++) {
                    a[mt][0] = h2u(__hfma2(u2h(a[mt][0]), sl, tl));
                    a[mt][1] = h2u(__hfma2(u2h(a[mt][1]), sl, tl));
                    a[mt][2] = h2u(__hfma2(u2h(a[mt][2]), sh, th));
                    a[mt][3] = h2u(__hfma2(u2h(a[mt][3]), sh, th));
                }
            }
            #pragma unroll
            for (int nt4 = 0; nt4 < 4; nt4++) {
                uint32_t b[4];
                uint32_t addr = bs + (uint32_t)(
                    (ks * 16 + l15) * 272 + (wn * 64 + nt4 * 16 + hi8) * 2);
                LDSM4T(b[0], b[1], b[2], b[3], addr);
                MMA16(acc[0][nt4 * 2 + 0], a[0], b[0], b[1]);
                MMA16(acc[1][nt4 * 2 + 0], a[1], b[0], b[1]);
                MMA16(acc[0][nt4 * 2 + 1], a[0], b[2], b[3]);
                MMA16(acc[1][nt4 * 2 + 1], a[1], b[2], b[3]);
            }
        }
        __syncthreads();
    }
    // smem free for epilogue staging

    if (ACT == 2) {
        float* smf = (float*)smem;
        #pragma unroll
        for (int mt = 0; mt < 2; mt++)
            #pragma unroll
            for (int half_ = 0; half_ < 2; half_++) {
                int lrow = wm * 32 + mt * 16 + r + half_ * 8;
                #pragma unroll
                for (int nt = 0; nt < 8; nt++) {
                    int col = wn * 64 + nt * 8 + 2 * t;
                    smf[col * 132 + lrow]       = acc[mt][nt][half_ * 2 + 0] + bp[bn + col];
                    smf[(col + 1) * 132 + lrow] = acc[mt][nt][half_ * 2 + 1] + bp[bn + col + 1];
                }
            }
        __syncthreads();
        float* out = (float*)Yp;
        int l0 = bm & (Lv - 1);
        int lq = tid & 7, ci = tid >> 3;
        #pragma unroll
        for (int it = 0; it < 4; it++) {
            int cc = ci + it * 32;
            const float* srow = smf + cc * 132;
            size_t gb = ((size_t)(bb * Cv + bn + cc)) * Lv + l0;
            float4* drow = (float4*)(out + gb);
            const float4* xrow = (const float4*)(xres + gb);
            #pragma unroll
            for (int k = 0; k < 4; k++) {
                int idx = lq + k * 8;
                float4 sv = *(const float4*)(srow + idx * 4);
                float4 xv = xrow[idx];
                sv.x += xv.x; sv.y += xv.y; sv.z += xv.z; sv.w += xv.w;
                drow[idx] = sv;
            }
        }
    } else {
        __half* smh = (__half*)smem;
        #pragma unroll
        for (int mt = 0; mt < 2; mt++)
            #pragma unroll
            for (int half_ = 0; half_ < 2; half_++) {
                int lrow = wm * 32 + mt * 16 + r + half_ * 8;
                #pragma unroll
                for (int nt = 0; nt < 8; nt++) {
                    int col = wn * 64 + nt * 8 + 2 * t;
                    float v0 = acc[mt][nt][half_ * 2 + 0] + bp[bn + col];
                    float v1 = acc[mt][nt][half_ * 2 + 1] + bp[bn + col + 1];
                    if (ACT == 1) {
                        v0 = v0 / (1.f + __expf(-1.702f * v0));
                        v1 = v1 / (1.f + __expf(-1.702f * v1));
                    }
                    *(__half2*)(smh + lrow * 136 + col) = __floats2half2_rn(v0, v1);
                }
            }
        __syncthreads();
        __half* Y = (__half*)Yp;
        int lq = tid & 7, mi = tid >> 3;
        #pragma unroll
        for (int it = 0; it < 4; it++) {
            int m = mi + it * 32;
            const uint4* srow = (const uint4*)(smh + m * 136);
            uint4* drow = (uint4*)(Y + (size_t)(bm + m) * Np + bn);
            drow[lq]     = srow[lq];
            drow[lq + 8] = srow[lq + 8];
        }
    }
}

// ---------------- KS=3 windowed attention, smem KV + coalesced Q/O --------
// block 256 = 8 warps (one head each); within a warp: lq=lane>>3 picks one of
// 4 l-positions, ld=lane&7 picks a 16B chunk of the 128B head vector.
__global__ __launch_bounds__(256) void attn_kernel(
    const __half* __restrict__ Q, const __half* __restrict__ KV,
    __half* __restrict__ O)
{
    extern __shared__ __align__(16) __half skv[];   // (TL+2) x KV_PITCH halfs
    int b  = blockIdx.y;
    int l0 = blockIdx.x * TL;
    int tid = threadIdx.x;

    // ---- cooperative load: 34 rows x 1024 halfs (clamped halo) ----
    #pragma unroll
    for (int it = 0; it < 17; it++) {
        int idx = tid + it * 256;                // 0 .. 4351
        int row = idx >> 7;                      // 0..33
        int q4  = idx & 127;                     // uint4 within row
        int gr  = l0 - 1 + row;
        gr = (gr < 0) ? 0 : ((gr > Lv - 1) ? Lv - 1 : gr);
        const uint4* src = (const uint4*)(KV + ((size_t)(b * Lv + gr)) * 1024);
        *(uint4*)(skv + row * KV_PITCH + q4 * 8) = src[q4];
    }
    __syncthreads();

    int h    = tid >> 5;
    int lane = tid & 31;
    int lq   = lane >> 3;     // 0..3: l within group
    int ld   = lane & 7;      // 0..7: 16B chunk within head

    #pragma unroll 2
    for (int g = 0; g < 8; g++) {
        int lrel = g * 4 + lq;                       // 0..31
        int l    = l0 + lrel;
        size_t rowq = ((size_t)(b * Lv + l)) * Cv + h * Dhv + ld * 8;
        uint4 qv = *(const uint4*)(Q + rowq);

        const __half* kb = skv + lrel * KV_PITCH + h * Dhv + ld * 8;
        uint4 k0 = *(const uint4*)(kb);
        uint4 k1 = *(const uint4*)(kb + KV_PITCH);
        uint4 k2 = *(const uint4*)(kb + 2 * KV_PITCH);

        float s0 = 0.f, s1 = 0.f, s2 = 0.f;
        {
            const __half2* qh = (const __half2*)&qv;
            const __half2* ah = (const __half2*)&k0;
            const __half2* ch = (const __half2*)&k1;
            const __half2* dh = (const __half2*)&k2;
            #pragma unroll
            for (int j = 0; j < 4; j++) {
                float2 qf = __half22float2(qh[j]);
                float2 af = __half22float2(ah[j]);
                float2 cf = __half22float2(ch[j]);
                float2 df = __half22float2(dh[j]);
                s0 += qf.x * af.x + qf.y * af.y;
                s1 += qf.x * cf.x + qf.y * cf.y;
                s2 += qf.x * df.x + qf.y * df.y;
            }
        }
        #pragma unroll
        for (int o = 4; o; o >>= 1) {
            s0 += __shfl_xor_sync(0xffffffffu, s0, o, 8);
            s1 += __shfl_xor_sync(0xffffffffu, s1, o, 8);
            s2 += __shfl_xor_sync(0xffffffffu, s2, o, 8);
        }
        float e0 = 0.f, e1 = 0.f, e2 = 0.f;
        if (ld == 0) {
            const float sc = 0.125f;
            float t0 = (l > 0)      ? s0 * sc : -1e9f;
            float t1 = s1 * sc;
            float t2 = (l < Lv - 1) ? s2 * sc : -1e9f;
            float mx = fmaxf(t1, fmaxf(t0, t2));
            e0 = expf(t0 - mx); e1 = expf(t1 - mx); e2 = expf(t2 - mx);
            float inv = 1.f / (e0 + e1 + e2);
            e0 *= inv; e1 *= inv; e2 *= inv;
        }
        e0 = __shfl_sync(0xffffffffu, e0, 0, 8);
        e1 = __shfl_sync(0xffffffffu, e1, 0, 8);
        e2 = __shfl_sync(0xffffffffu, e2, 0, 8);

        const __half* vb = kb + 512;
        uint4 v0 = *(const uint4*)(vb);
        uint4 v1 = *(const uint4*)(vb + KV_PITCH);
        uint4 v2 = *(const uint4*)(vb + 2 * KV_PITCH);
        uint4 ov;
        {
            const __half2* ah = (const __half2*)&v0;
            const __half2* ch = (const __half2*)&v1;
            const __half2* dh = (const __half2*)&v2;
            __half2* oh = (__half2*)&ov;
            #pragma unroll
            for (int j = 0; j < 4; j++) {
                float2 af = __half22float2(ah[j]);
                float2 cf = __half22float2(ch[j]);
                float2 df = __half22float2(dh[j]);
                oh[j] = __floats2half2_rn(e0 * af.x + e1 * cf.x + e2 * df.x,
                                          e0 * af.y + e1 * cf.y + e2 * df.y);
            }
        }
        *(uint4*)(O + rowq) = ov;
    }
}

// ---------------- launch ---------------------------------------------------
extern "C" void kernel_launch(void* const* d_in, const int* in_sizes, int n_in,
                              void* d_out, int out_size)
{
    const float* q   = (const float*)d_in[0];
    const float* x   = (const float*)d_in[1];
    const float* g1  = (const float*)d_in[2];
    const float* b1  = (const float*)d_in[3];
    const float* Wq  = (const float*)d_in[4];
    const float* bq  = (const float*)d_in[5];
    const float* Wk  = (const float*)d_in[6];
    const float* bk  = (const float*)d_in[7];
    const float* Wv  = (const float*)d_in[8];
    const float* bv  = (const float*)d_in[9];
    const float* Wo  = (const float*)d_in[10];
    const float* bo  = (const float*)d_in[11];
    const float* g2  = (const float*)d_in[12];
    const float* b2  = (const float*)d_in[13];
    const float* Wfc = (const float*)d_in[14];
    const float* bfc = (const float*)d_in[15];
    const float* Wpr = (const float*)d_in[16];
    const float* bpr = (const float*)d_in[17];
    float* out = (float*)d_out;

    __half *QT, *XT, *Qb, *KVb, *Ob, *Yb, *Ub, *WT, *S2h, *T2h;
    float *BKV, *S1, *T1;
    cudaGetSymbolAddress((void**)&QT,  g_QT);
    cudaGetSymbolAddress((void**)&XT,  g_XT);
    cudaGetSymbolAddress((void**)&Qb,  g_Q);
    cudaGetSymbolAddress((void**)&KVb, g_KV);
    cudaGetSymbolAddress((void**)&Ob,  g_O);
    cudaGetSymbolAddress((void**)&Yb,  g_Y);
    cudaGetSymbolAddress((void**)&Ub,  g_U);
    cudaGetSymbolAddress((void**)&WT,  g_WT);
    cudaGetSymbolAddress((void**)&BKV, g_BKV);
    cudaGetSymbolAddress((void**)&S1,  g_S1);
    cudaGetSymbolAddress((void**)&T1,  g_T1);
    cudaGetSymbolAddress((void**)&S2h, g_S2h);
    cudaGetSymbolAddress((void**)&T2h, g_T2h);

    #define SETSM(k, sz) cudaFuncSetAttribute(k, cudaFuncAttributeMaxDynamicSharedMemorySize, sz)
    SETSM((mma_gemm<0, false>), SMEM_GEMM);
    SETSM((mma_gemm<1, true >), SMEM_GEMM);
    SETSM((mma_gemm<2, false>), SMEM_GEMM);
    SETSM((mma_gemm<3, false>), SMEM_GEMM);
    SETSM(attn_kernel, ATTN_SMEM);

    // 1) norm1 stats + merged staging transpose + weight conversion
    rowstats_kernel<<<Bv * Cv, 256>>>(x, g1, b1, S1, T1);
    transpose_qx<<<dim3(Lv / 32, Cv / 32, Bv), dim3(32, 8)>>>(q, x, S1, T1, QT, XT);
    w2h_all<<<2048, 256>>>(Wq, Wk, Wv, Wo, Wfc, Wpr, bk, bv, WT, BKV);

    const int Mt = (Bv * Lv) / BM;   // 256
    dim3 g512(512 / BN, Mt), g1024(1024 / BN, Mt), gqkv(12, Mt);

    // 2) combined Q + KV projections in one launch
    mma_gemm<3, false><<<gqkv, 256, SMEM_GEMM>>>(
        QT, WT + WQ_OFF, bq, Qb, 512, 512, nullptr, nullptr, nullptr,
        XT, WT + WKV_OFF, BKV, KVb);

    // 3) windowed attention (smem KV, coalesced Q/O)
    attn_kernel<<<dim3(Lv / TL, Bv), 256, ATTN_SMEM>>>(Qb, KVb, Ob);

    // 4) output projection
    mma_gemm<0, false><<<g512, 256, SMEM_GEMM>>>(
        Ob, WT + WO_OFF, bo, Yb, 512, 512, nullptr, nullptr, nullptr,
        nullptr, nullptr, nullptr, nullptr);

    // 5) norm2 stats -> fp16 affine tables (applied inside fc GEMM)
    colstats_kernel<<<dim3(Cv / 64, Bv), 256>>>(Yb, g2, b2, S2h, T2h);

    // 6) MLP: fc + QuickGELU with fused norm2, then proj + residual + transpose
    mma_gemm<1, true><<<g1024, 256, SMEM_GEMM>>>(
        Yb, WT + WFC_OFF, bfc, Ub, 512, 1024, nullptr, S2h, T2h,
        nullptr, nullptr, nullptr, nullptr);
    mma_gemm<2, false><<<g512, 256, SMEM_GEMM>>>(
        Ub, WT + WPR_OFF, bpr, out, 1024, 512, x, nullptr, nullptr,
        nullptr, nullptr, nullptr, nullptr);
}

// round 17
// speedup vs baseline: 1.0314x; 1.0314x over previous
#include <cuda_runtime.h>
#include <cuda_fp16.h>
#include <math.h>
#include <stdint.h>

// ---------------- problem constants ----------------
constexpr int Bv  = 16;
constexpr int Cv  = 512;
constexpr int Lv  = 2048;
constexpr int Hv  = 8;
constexpr int Dhv = 64;

// ---------------- fp16 mma GEMM config ----------------
constexpr int BM  = 128;
constexpr int BN  = 128;
constexpr int BKK = 32;
constexpr int A_HALFS  = BM * 40;            // 80B rows, conflict-free
constexpr int B_HALFS  = BKK * 136;          // 272B rows, conflict-free
constexpr int STAGE_BYTES = (A_HALFS + B_HALFS) * 2;   // 18944
constexpr int STAGES = 4;
constexpr int SMEM_GEMM = STAGES * STAGE_BYTES;        // 75776

// ---------------- attention smem config ----------------
constexpr int TL = 32;                       // l-positions per block
constexpr int KV_PITCH = 1032;               // halfs; 2064B = 516 words ≡ 4 (mod 32)
constexpr int ATTN_SMEM = (TL + 2) * KV_PITCH * 2;   // 70176 bytes

// ---------------- scratch ----------------
__device__ __half g_QT[16777216];
__device__ __half g_XT[16777216];
__device__ __half g_Q[16777216];
__device__ __half g_KV[33554432];  // [M,1024]: cols 0-511 K, 512-1023 V
__device__ __half g_O[16777216];
__device__ __half g_Y[16777216];
__device__ __half g_U[33554432];
__device__ __half g_WT[2097152];
__device__ float  g_BKV[1024];
__device__ float  g_S1[Bv*Cv], g_T1[Bv*Cv];
__device__ float  g_CS[Bv*Cv], g_CQ[Bv*Cv];     // norm2 sum / sumsq accumulators
__device__ __half g_S2h[Bv*Cv], g_T2h[Bv*Cv];   // norm2 affine, fp16 tables

constexpr int WQ_OFF  = 0;
constexpr int WKV_OFF = 262144;    // interleaved [512 x 1024]
constexpr int WO_OFF  = 786432;
constexpr int WFC_OFF = 1048576;
constexpr int WPR_OFF = 1572864;

// ---------------- helpers ----------------
__device__ __forceinline__ uint32_t smem_u32(const void* p) {
    uint32_t a;
    asm("{ .reg .u64 t; cvta.to.shared.u64 t, %1; cvt.u32.u64 %0, t; }" : "=r"(a) : "l"(p));
    return a;
}
__device__ __forceinline__ uint32_t h2u(__half2 h) {
    union { __half2 h; uint32_t u; } c; c.h = h; return c.u;
}
__device__ __forceinline__ __half2 u2h(uint32_t u) {
    union { uint32_t u; __half2 h; } c; c.u = u; return c.h;
}
__device__ __forceinline__ void cpa16(uint32_t dst, const void* src) {
    asm volatile("cp.async.cg.shared.global [%0], [%1], 16;" :: "r"(dst), "l"(src) : "memory");
}
template<int NW>
__device__ __forceinline__ void cpwait() {
    asm volatile("cp.async.wait_group %0;" :: "n"(NW) : "memory");
}

#define LDSM4(r0, r1, r2, r3, addr)                                          \
    asm volatile("ldmatrix.sync.aligned.m8n8.x4.shared.b16 {%0,%1,%2,%3}, [%4];" \
        : "=r"(r0), "=r"(r1), "=r"(r2), "=r"(r3) : "r"(addr))

#define LDSM4T(r0, r1, r2, r3, addr)                                         \
    asm volatile("ldmatrix.sync.aligned.m8n8.x4.trans.shared.b16 {%0,%1,%2,%3}, [%4];" \
        : "=r"(r0), "=r"(r1), "=r"(r2), "=r"(r3) : "r"(addr))

#define MMA16(d, a, b0, b1)                                                  \
    asm volatile("mma.sync.aligned.m16n8k16.row.col.f32.f16.f16.f32 "        \
        "{%0,%1,%2,%3}, {%4,%5,%6,%7}, {%8,%9}, {%0,%1,%2,%3};"              \
        : "+f"((d)[0]), "+f"((d)[1]), "+f"((d)[2]), "+f"((d)[3])             \
        : "r"((a)[0]), "r"((a)[1]), "r"((a)[2]), "r"((a)[3]),                \
          "r"(b0), "r"(b1))

// ---------------- instance-norm stats over rows of x (B,C,L) -------------
__global__ void rowstats_kernel(const float* __restrict__ x,
                                const float* __restrict__ gamma,
                                const float* __restrict__ beta,
                                float* __restrict__ s, float* __restrict__ t)
{
    int row = blockIdx.x;
    const float4* p = (const float4*)(x + (size_t)row * Lv);
    float sum = 0.f, sq = 0.f;
    for (int i = threadIdx.x; i < Lv / 4; i += blockDim.x) {
        float4 v = p[i];
        sum += v.x + v.y + v.z + v.w;
        sq  += v.x*v.x + v.y*v.y + v.z*v.z + v.w*v.w;
    }
    __shared__ float ssum[8], ssq[8];
    for (int o = 16; o; o >>= 1) {
        sum += __shfl_down_sync(0xffffffffu, sum, o);
        sq  += __shfl_down_sync(0xffffffffu, sq,  o);
    }
    int wid = threadIdx.x >> 5, lane = threadIdx.x & 31;
    if (lane == 0) { ssum[wid] = sum; ssq[wid] = sq; }
    __syncthreads();
    if (wid == 0) {
        sum = lane < (blockDim.x >> 5) ? ssum[lane] : 0.f;
        sq  = lane < (blockDim.x >> 5) ? ssq[lane]  : 0.f;
        for (int o = 4; o; o >>= 1) {
            sum += __shfl_down_sync(0xffffffffu, sum, o);
            sq  += __shfl_down_sync(0xffffffffu, sq,  o);
        }
        if (lane == 0) {
            float mean = sum / (float)Lv;
            float var  = sq / (float)Lv - mean * mean;
            float rstd = rsqrtf(var + 1e-5f);
            int c = row % Cv;
            float sv = gamma[c] * rstd;
            s[row] = sv;
            t[row] = beta[c] - mean * sv;
        }
    }
}

// ---------------- finalize norm2 stats from accumulators ------------------
__global__ void finalize_stats(const float* __restrict__ CS,
                               const float* __restrict__ CQ,
                               const float* __restrict__ gamma,
                               const float* __restrict__ beta,
                               __half* __restrict__ sh, __half* __restrict__ th)
{
    int c = threadIdx.x;
    int b = blockIdx.x;
    float sum = CS[b * Cv + c], sq = CQ[b * Cv + c];
    float mean = sum / (float)Lv;
    float var  = sq / (float)Lv - mean * mean;
    float rstd = rsqrtf(var + 1e-5f);
    float sv = gamma[c] * rstd;
    sh[b * Cv + c] = __float2half(sv);
    th[b * Cv + c] = __float2half(beta[c] - mean * sv);
}

// ---------------- merged transpose (B,C,L) f32 -> (B*L,C) f16 ------------
__global__ void transpose_qx(const float* __restrict__ qsrc,
                             const float* __restrict__ xsrc,
                             const float* __restrict__ s,
                             const float* __restrict__ t,
                             __half* __restrict__ QT,
                             __half* __restrict__ XT)
{
    __shared__ float sm[32][33];
    int b  = blockIdx.z;
    int c0 = blockIdx.y * 32;
    int l0 = blockIdx.x * 32;
    int tx = threadIdx.x, ty = threadIdx.y;
    #pragma unroll
    for (int i = 0; i < 4; i++) {
        int c = c0 + ty + i * 8;
        sm[ty + i * 8][tx] = qsrc[((size_t)(b * Cv + c)) * Lv + l0 + tx];
    }
    __syncthreads();
    #pragma unroll
    for (int i = 0; i < 4; i++) {
        int l = l0 + ty + i * 8;
        QT[((size_t)(b * Lv + l)) * Cv + c0 + tx] = __float2half(sm[tx][ty + i * 8]);
    }
    __syncthreads();
    #pragma unroll
    for (int i = 0; i < 4; i++) {
        int c = c0 + ty + i * 8;
        float v = xsrc[((size_t)(b * Cv + c)) * Lv + l0 + tx];
        sm[ty + i * 8][tx] = v * s[b * Cv + c] + t[b * Cv + c];
    }
    __syncthreads();
    #pragma unroll
    for (int i = 0; i < 4; i++) {
        int l = l0 + ty + i * 8;
        XT[((size_t)(b * Lv + l)) * Cv + c0 + tx] = __float2half(sm[tx][ty + i * 8]);
    }
}

// ---------------- all weights fp32 -> fp16 + zero stat accumulators -------
__global__ void w2h_all(const float* __restrict__ Wq, const float* __restrict__ Wk,
                        const float* __restrict__ Wv, const float* __restrict__ Wo,
                        const float* __restrict__ Wfc, const float* __restrict__ Wpr,
                        const float* __restrict__ bk, const float* __restrict__ bv,
                        __half* __restrict__ WT, float* __restrict__ bkv,
                        float* __restrict__ CS, float* __restrict__ CQ)
{
    int i = blockIdx.x * blockDim.x + threadIdx.x;   // float4 index, 524288 total
    if (i < 1024) bkv[i] = (i < 512) ? bk[i] : bv[i - 512];
    if (i < 8192) { CS[i] = 0.f; CQ[i] = 0.f; }
    const float* src; size_t dsth;
    if (i < 65536)       { src = Wq + (size_t)i * 4;  dsth = WQ_OFF + (size_t)i * 4; }
    else if (i < 131072) { int rel = i - 65536;  int k = rel >> 7, n4 = rel & 127;
                           src = Wk + (size_t)rel * 4;
                           dsth = WKV_OFF + (size_t)k * 1024 + n4 * 4; }
    else if (i < 196608) { int rel = i - 131072; int k = rel >> 7, n4 = rel & 127;
                           src = Wv + (size_t)rel * 4;
                           dsth = WKV_OFF + (size_t)k * 1024 + 512 + n4 * 4; }
    else if (i < 262144) { int rel = i - 196608; src = Wo + (size_t)rel * 4;
                           dsth = WO_OFF + (size_t)rel * 4; }
    else if (i < 393216) { int rel = i - 262144; src = Wfc + (size_t)rel * 4;
                           dsth = WFC_OFF + (size_t)rel * 4; }
    else                 { int rel = i - 393216; src = Wpr + (size_t)rel * 4;
                           dsth = WPR_OFF + (size_t)rel * 4; }
    float4 v = *(const float4*)src;
    *(__half2*)(WT + dsth)     = __floats2half2_rn(v.x, v.y);
    *(__half2*)(WT + dsth + 2) = __floats2half2_rn(v.z, v.w);
}

// ---------------- fp16 mma.sync GEMM with coalesced smem epilogue ---------
// Y = act( A'[M,K]h @ W[K,N]h + bias_f ),  A' = ANORM ? A*s+t (per b,k) : A
// ACT 0: none (half out)  ACT 1: QuickGELU (half out)
// ACT 2: residual + transpose to (B,C,L) f32 out
// ACT 3: combined Q|KV launch — blockIdx.x<4 uses (A,W,bias,Yv,N=512),
//        otherwise (A2,W2,bias2,Yv2,N=1024); epilogue = ACT0 path.
// ACT 4: half out + per-(b,c) sum/sumsq atomics into CS/CQ (norm2 fusion)
// 4-stage cp.async pipeline, prefetch depth 3 (R11-validated config).
template<int ACT, bool ANORM>
__global__ void __launch_bounds__(256)
mma_gemm(const __half* __restrict__ A, const __half* __restrict__ W,
         const float* __restrict__ bias, void* __restrict__ Yv,
         int K, int N, const float* __restrict__ xres,
         const __half* __restrict__ nS, const __half* __restrict__ nT,
         const __half* __restrict__ A2, const __half* __restrict__ W2,
         const float* __restrict__ bias2, void* __restrict__ Yv2,
         float* __restrict__ CS, float* __restrict__ CQ)
{
    extern __shared__ __align__(16) char smem[];
    const int tid  = threadIdx.x;
    const int bm   = blockIdx.y * BM;
    const int lane = tid & 31, warp = tid >> 5;
    const int wm   = warp & 3, wn = warp >> 2;
    const int r    = lane >> 2, t = lane & 3;
    const uint32_t sbase = smem_u32(smem);
    const int nch = K / BKK;
    const int bb  = bm >> 11;

    // resolve operand set (ACT3 branches per blockIdx.x)
    const __half* Ap = A;  const __half* Wp = W;
    const float*  bp = bias;
    void* Yp = Yv;
    int Np = N;
    int bn = blockIdx.x * BN;
    if (ACT == 3 && blockIdx.x >= 4) {
        Ap = A2; Wp = W2; bp = bias2; Yp = Yv2; Np = 1024;
        bn = (blockIdx.x - 4) * BN;
    }
    if (ANORM) { nS += bb * Cv; nT += bb * Cv; }
    const __half2* nS2 = (const __half2*)nS;
    const __half2* nT2 = (const __half2*)nT;

    float acc[2][8][4];
    #pragma unroll
    for (int mt = 0; mt < 2; mt++)
        #pragma unroll
        for (int nt = 0; nt < 8; nt++)
            #pragma unroll
            for (int j = 0; j < 4; j++) acc[mt][nt][j] = 0.f;

    auto issue = [&](int c) {
        uint32_t as = sbase + (uint32_t)((c % STAGES) * STAGE_BYTES);
        uint32_t bs = as + A_HALFS * 2;
        const __half* ga = Ap + (size_t)bm * K + c * BKK;
        #pragma unroll
        for (int i = 0; i < 2; i++) {
            int id = tid + i * 256;
            int m = id >> 2, q = id & 3;
            cpa16(as + (uint32_t)(m * 80 + q * 16), ga + (size_t)m * K + q * 8);
        }
        const __half* gb = Wp + (size_t)(c * BKK) * Np + bn;
        #pragma unroll
        for (int i = 0; i < 2; i++) {
            int id = tid + i * 256;
            int k = id >> 4, q = id & 15;
            cpa16(bs + (uint32_t)(k * 272 + q * 16), gb + (size_t)k * Np + q * 8);
        }
        asm volatile("cp.async.commit_group;" ::: "memory");
    };

    issue(0); issue(1); issue(2);

    const int l15 = lane & 15;
    const int hi8 = (lane >> 4) << 3;

    for (int c = 0; c < nch; c++) {
        if (c + 2 < nch)      cpwait<2>();
        else if (c + 1 < nch) cpwait<1>();
        else                  cpwait<0>();
        __syncthreads();
        if (c + 3 < nch) issue(c + 3);

        uint32_t as = sbase + (uint32_t)((c % STAGES) * STAGE_BYTES);
        uint32_t bs = as + A_HALFS * 2;

        #pragma unroll
        for (int ks = 0; ks < 2; ks++) {
            uint32_t a[2][4];
            #pragma unroll
            for (int mt = 0; mt < 2; mt++) {
                uint32_t addr = as + (uint32_t)(
                    (wm * 32 + mt * 16 + l15) * 80 + ks * 32 + hi8 * 2);
                LDSM4(a[mt][0], a[mt][1], a[mt][2], a[mt][3], addr);
            }
            if (ANORM) {
                // A-frag k map: regs {0,1} -> k = 2t,2t+1 ; {2,3} -> k+8
                int kidx = c * 16 + ks * 8 + t;      // half2 index
                __half2 sl = nS2[kidx],     tl = nT2[kidx];
                __half2 sh = nS2[kidx + 4], th = nT2[kidx + 4];
                #pragma unroll
                for (int mt = 0; mt < 2; mt++) {
                    a[mt][0] = h2u(__hfma2(u2h(a[mt][0]), sl, tl));
                    a[mt][1] = h2u(__hfma2(u2h(a[mt][1]), sl, tl));
                    a[mt][2] = h2u(__hfma2(u2h(a[mt][2]), sh, th));
                    a[mt][3] = h2u(__hfma2(u2h(a[mt][3]), sh, th));
                }
            }
            #pragma unroll
            for (int nt4 = 0; nt4 < 4; nt4++) {
                uint32_t b[4];
                uint32_t addr = bs + (uint32_t)(
                    (ks * 16 + l15) * 272 + (wn * 64 + nt4 * 16 + hi8) * 2);
                LDSM4T(b[0], b[1], b[2], b[3], addr);
                MMA16(acc[0][nt4 * 2 + 0], a[0], b[0], b[1]);
                MMA16(acc[1][nt4 * 2 + 0], a[1], b[0], b[1]);
                MMA16(acc[0][nt4 * 2 + 1], a[0], b[2], b[3]);
                MMA16(acc[1][nt4 * 2 + 1], a[1], b[2], b[3]);
            }
        }
        __syncthreads();
    }
    // smem free for epilogue staging

    if (ACT == 2) {
        float* smf = (float*)smem;
        #pragma unroll
        for (int mt = 0; mt < 2; mt++)
            #pragma unroll
            for (int half_ = 0; half_ < 2; half_++) {
                int lrow = wm * 32 + mt * 16 + r + half_ * 8;
                #pragma unroll
                for (int nt = 0; nt < 8; nt++) {
                    int col = wn * 64 + nt * 8 + 2 * t;
                    smf[col * 132 + lrow]       = acc[mt][nt][half_ * 2 + 0] + bp[bn + col];
                    smf[(col + 1) * 132 + lrow] = acc[mt][nt][half_ * 2 + 1] + bp[bn + col + 1];
                }
            }
        __syncthreads();
        float* out = (float*)Yp;
        int l0 = bm & (Lv - 1);
        int lq = tid & 7, ci = tid >> 3;
        #pragma unroll
        for (int it = 0; it < 4; it++) {
            int cc = ci + it * 32;
            const float* srow = smf + cc * 132;
            size_t gb = ((size_t)(bb * Cv + bn + cc)) * Lv + l0;
            float4* drow = (float4*)(out + gb);
            const float4* xrow = (const float4*)(xres + gb);
            #pragma unroll
            for (int k = 0; k < 4; k++) {
                int idx = lq + k * 8;
                float4 sv = *(const float4*)(srow + idx * 4);
                float4 xv = xrow[idx];
                sv.x += xv.x; sv.y += xv.y; sv.z += xv.z; sv.w += xv.w;
                drow[idx] = sv;
            }
        }
    } else {
        __half* smh = (__half*)smem;
        #pragma unroll
        for (int mt = 0; mt < 2; mt++)
            #pragma unroll
            for (int half_ = 0; half_ < 2; half_++) {
                int lrow = wm * 32 + mt * 16 + r + half_ * 8;
                #pragma unroll
                for (int nt = 0; nt < 8; nt++) {
                    int col = wn * 64 + nt * 8 + 2 * t;
                    float v0 = acc[mt][nt][half_ * 2 + 0] + bp[bn + col];
                    float v1 = acc[mt][nt][half_ * 2 + 1] + bp[bn + col + 1];
                    if (ACT == 1) {
                        v0 = v0 / (1.f + __expf(-1.702f * v0));
                        v1 = v1 / (1.f + __expf(-1.702f * v1));
                    }
                    *(__half2*)(smh + lrow * 136 + col) = __floats2half2_rn(v0, v1);
                }
            }
        __syncthreads();
        __half* Y = (__half*)Yp;
        int lq = tid & 7, mi = tid >> 3;
        #pragma unroll
        for (int it = 0; it < 4; it++) {
            int m = mi + it * 32;
            const uint4* srow = (const uint4*)(smh + m * 136);
            uint4* drow = (uint4*)(Y + (size_t)(bm + m) * Np + bn);
            drow[lq]     = srow[lq];
            drow[lq + 8] = srow[lq + 8];
        }
        if (ACT == 4) {
            // fused norm2 partial stats: 2 threads per column, 64 rows each
            int colc = tid & 127, seg = tid >> 7;
            float sum = 0.f, sq = 0.f;
            #pragma unroll 8
            for (int m = seg * 64; m < seg * 64 + 64; m++) {
                float v = __half2float(smh[m * 136 + colc]);
                sum += v; sq += v * v;
            }
            atomicAdd(&CS[bb * Cv + bn + colc], sum);
            atomicAdd(&CQ[bb * Cv + bn + colc], sq);
        }
    }
}

// ---------------- KS=3 windowed attention, smem KV + coalesced Q/O --------
// block 256 = 8 warps (one head each); within a warp: lq=lane>>3 picks one of
// 4 l-positions, ld=lane&7 picks a 16B chunk of the 128B head vector.
__global__ __launch_bounds__(256) void attn_kernel(
    const __half* __restrict__ Q, const __half* __restrict__ KV,
    __half* __restrict__ O)
{
    extern __shared__ __align__(16) __half skv[];   // (TL+2) x KV_PITCH halfs
    int b  = blockIdx.y;
    int l0 = blockIdx.x * TL;
    int tid = threadIdx.x;

    // ---- cooperative load: 34 rows x 1024 halfs (clamped halo) ----
    #pragma unroll
    for (int it = 0; it < 17; it++) {
        int idx = tid + it * 256;                // 0 .. 4351
        int row = idx >> 7;                      // 0..33
        int q4  = idx & 127;                     // uint4 within row
        int gr  = l0 - 1 + row;
        gr = (gr < 0) ? 0 : ((gr > Lv - 1) ? Lv - 1 : gr);
        const uint4* src = (const uint4*)(KV + ((size_t)(b * Lv + gr)) * 1024);
        *(uint4*)(skv + row * KV_PITCH + q4 * 8) = src[q4];
    }
    __syncthreads();

    int h    = tid >> 5;
    int lane = tid & 31;
    int lq   = lane >> 3;     // 0..3: l within group
    int ld   = lane & 7;      // 0..7: 16B chunk within head

    #pragma unroll 2
    for (int g = 0; g < 8; g++) {
        int lrel = g * 4 + lq;                       // 0..31
        int l    = l0 + lrel;
        size_t rowq = ((size_t)(b * Lv + l)) * Cv + h * Dhv + ld * 8;
        uint4 qv = *(const uint4*)(Q + rowq);

        const __half* kb = skv + lrel * KV_PITCH + h * Dhv + ld * 8;
        uint4 k0 = *(const uint4*)(kb);
        uint4 k1 = *(const uint4*)(kb + KV_PITCH);
        uint4 k2 = *(const uint4*)(kb + 2 * KV_PITCH);

        float s0 = 0.f, s1 = 0.f, s2 = 0.f;
        {
            const __half2* qh = (const __half2*)&qv;
            const __half2* ah = (const __half2*)&k0;
            const __half2* ch = (const __half2*)&k1;
            const __half2* dh = (const __half2*)&k2;
            #pragma unroll
            for (int j = 0; j < 4; j++) {
                float2 qf = __half22float2(qh[j]);
                float2 af = __half22float2(ah[j]);
                float2 cf = __half22float2(ch[j]);
                float2 df = __half22float2(dh[j]);
                s0 += qf.x * af.x + qf.y * af.y;
                s1 += qf.x * cf.x + qf.y * cf.y;
                s2 += qf.x * df.x + qf.y * df.y;
            }
        }
        #pragma unroll
        for (int o = 4; o; o >>= 1) {
            s0 += __shfl_xor_sync(0xffffffffu, s0, o, 8);
            s1 += __shfl_xor_sync(0xffffffffu, s1, o, 8);
            s2 += __shfl_xor_sync(0xffffffffu, s2, o, 8);
        }
        float e0 = 0.f, e1 = 0.f, e2 = 0.f;
        if (ld == 0) {
            const float sc = 0.125f;
            float t0 = (l > 0)      ? s0 * sc : -1e9f;
            float t1 = s1 * sc;
            float t2 = (l < Lv - 1) ? s2 * sc : -1e9f;
            float mx = fmaxf(t1, fmaxf(t0, t2));
            e0 = expf(t0 - mx); e1 = expf(t1 - mx); e2 = expf(t2 - mx);
            float inv = 1.f / (e0 + e1 + e2);
            e0 *= inv; e1 *= inv; e2 *= inv;
        }
        e0 = __shfl_sync(0xffffffffu, e0, 0, 8);
        e1 = __shfl_sync(0xffffffffu, e1, 0, 8);
        e2 = __shfl_sync(0xffffffffu, e2, 0, 8);

        const __half* vb = kb + 512;
        uint4 v0 = *(const uint4*)(vb);
        uint4 v1 = *(const uint4*)(vb + KV_PITCH);
        uint4 v2 = *(const uint4*)(vb + 2 * KV_PITCH);
        uint4 ov;
        {
            const __half2* ah = (const __half2*)&v0;
            const __half2* ch = (const __half2*)&v1;
            const __half2* dh = (const __half2*)&v2;
            __half2* oh = (__half2*)&ov;
            #pragma unroll
            for (int j = 0; j < 4; j++) {
                float2 af = __half22float2(ah[j]);
                float2 cf = __half22float2(ch[j]);
                float2 df = __half22float2(dh[j]);
                oh[j] = __floats2half2_rn(e0 * af.x + e1 * cf.x + e2 * df.x,
                                          e0 * af.y + e1 * cf.y + e2 * df.y);
            }
        }
        *(uint4*)(O + rowq) = ov;
    }
}

// ---------------- launch ---------------------------------------------------
extern "C" void kernel_launch(void* const* d_in, const int* in_sizes, int n_in,
                              void* d_out, int out_size)
{
    const float* q   = (const float*)d_in[0];
    const float* x   = (const float*)d_in[1];
    const float* g1  = (const float*)d_in[2];
    const float* b1  = (const float*)d_in[3];
    const float* Wq  = (const float*)d_in[4];
    const float* bq  = (const float*)d_in[5];
    const float* Wk  = (const float*)d_in[6];
    const float* bk  = (const float*)d_in[7];
    const float* Wv  = (const float*)d_in[8];
    const float* bv  = (const float*)d_in[9];
    const float* Wo  = (const float*)d_in[10];
    const float* bo  = (const float*)d_in[11];
    const float* g2  = (const float*)d_in[12];
    const float* b2  = (const float*)d_in[13];
    const float* Wfc = (const float*)d_in[14];
    const float* bfc = (const float*)d_in[15];
    const float* Wpr = (const float*)d_in[16];
    const float* bpr = (const float*)d_in[17];
    float* out = (float*)d_out;

    __half *QT, *XT, *Qb, *KVb, *Ob, *Yb, *Ub, *WT, *S2h, *T2h;
    float *BKV, *S1, *T1, *CS, *CQ;
    cudaGetSymbolAddress((void**)&QT,  g_QT);
    cudaGetSymbolAddress((void**)&XT,  g_XT);
    cudaGetSymbolAddress((void**)&Qb,  g_Q);
    cudaGetSymbolAddress((void**)&KVb, g_KV);
    cudaGetSymbolAddress((void**)&Ob,  g_O);
    cudaGetSymbolAddress((void**)&Yb,  g_Y);
    cudaGetSymbolAddress((void**)&Ub,  g_U);
    cudaGetSymbolAddress((void**)&WT,  g_WT);
    cudaGetSymbolAddress((void**)&BKV, g_BKV);
    cudaGetSymbolAddress((void**)&S1,  g_S1);
    cudaGetSymbolAddress((void**)&T1,  g_T1);
    cudaGetSymbolAddress((void**)&CS,  g_CS);
    cudaGetSymbolAddress((void**)&CQ,  g_CQ);
    cudaGetSymbolAddress((void**)&S2h, g_S2h);
    cudaGetSymbolAddress((void**)&T2h, g_T2h);

    #define SETSM(k, sz) cudaFuncSetAttribute(k, cudaFuncAttributeMaxDynamicSharedMemorySize, sz)
    SETSM((mma_gemm<1, true >), SMEM_GEMM);
    SETSM((mma_gemm<2, false>), SMEM_GEMM);
    SETSM((mma_gemm<3, false>), SMEM_GEMM);
    SETSM((mma_gemm<4, false>), SMEM_GEMM);
    SETSM(attn_kernel, ATTN_SMEM);

    // 1) norm1 stats + merged staging transpose + weight conversion (+ zero CS/CQ)
    rowstats_kernel<<<Bv * Cv, 256>>>(x, g1, b1, S1, T1);
    transpose_qx<<<dim3(Lv / 32, Cv / 32, Bv), dim3(32, 8)>>>(q, x, S1, T1, QT, XT);
    w2h_all<<<2048, 256>>>(Wq, Wk, Wv, Wo, Wfc, Wpr, bk, bv, WT, BKV, CS, CQ);

    const int Mt = (Bv * Lv) / BM;   // 256
    dim3 g512(512 / BN, Mt), g1024(1024 / BN, Mt), gqkv(12, Mt);

    // 2) combined Q + KV projections in one launch
    mma_gemm<3, false><<<gqkv, 256, SMEM_GEMM>>>(
        QT, WT + WQ_OFF, bq, Qb, 512, 512, nullptr, nullptr, nullptr,
        XT, WT + WKV_OFF, BKV, KVb, nullptr, nullptr);

    // 3) windowed attention (smem KV, coalesced Q/O)
    attn_kernel<<<dim3(Lv / TL, Bv), 256, ATTN_SMEM>>>(Qb, KVb, Ob);

    // 4) output projection with fused norm2 partial stats
    mma_gemm<4, false><<<g512, 256, SMEM_GEMM>>>(
        Ob, WT + WO_OFF, bo, Yb, 512, 512, nullptr, nullptr, nullptr,
        nullptr, nullptr, nullptr, nullptr, CS, CQ);

    // 5) finalize norm2 affine tables
    finalize_stats<<<Bv, Cv>>>(CS, CQ, g2, b2, S2h, T2h);

    // 6) MLP: fc + QuickGELU with fused norm2, then proj + residual + transpose
    mma_gemm<1, true><<<g1024, 256, SMEM_GEMM>>>(
        Yb, WT + WFC_OFF, bfc, Ub, 512, 1024, nullptr, S2h, T2h,
        nullptr, nullptr, nullptr, nullptr, nullptr, nullptr);
    mma_gemm<2, false><<<g512, 256, SMEM_GEMM>>>(
        Ub, WT + WPR_OFF, bpr, out, 1024, 512, x, nullptr, nullptr,
        nullptr, nullptr, nullptr, nullptr, nullptr, nullptr);
}